// round 13
// baseline (speedup 1.0000x reference)
#include <cuda_runtime.h>
#include <cuda_fp16.h>
#include <cstdint>

#define MAX_ATOMS 50000
#define DD 256
#define NB 16

#define BM 128
#define BN 128
#define BKH 32            // K chunk in halfs (64 B/row fp16, 128 B/row fp32 src)
#define NCHH (DD / BKH)   // 8 chunks
#define RW 20             // 4B words per smem row (16 data + 4 pad; conflict-free)

// Scratch: fp16 h (row 0 zeroed), fp16 W.
__device__ __half g_hh[(size_t)MAX_ATOMS * DD];
__device__ __half g_Wh[DD * DD];

// ---------------------------------------------------------------------------
// helpers (sm_80-baseline features only — harness builds plain sm_103 PTX)
// ---------------------------------------------------------------------------
__device__ __forceinline__ uint32_t smem_u32(const void* p) {
    uint32_t a;
    asm("{ .reg .u64 t; cvta.to.shared.u64 t, %1; cvt.u32.u64 %0, t; }" : "=r"(a) : "l"(p));
    return a;
}
__device__ __forceinline__ uint32_t h2u(__half2 h) {
    return *reinterpret_cast<uint32_t*>(&h);   // register-level bit cast
}
__device__ __forceinline__ void ldsm4(uint32_t r[4], uint32_t a) {
    asm volatile("ldmatrix.sync.aligned.m8n8.x4.shared.b16 {%0,%1,%2,%3}, [%4];"
                 : "=r"(r[0]), "=r"(r[1]), "=r"(r[2]), "=r"(r[3]) : "r"(a));
}
__device__ __forceinline__ void cp16(uint32_t dst, const void* src, uint32_t nbytes) {
    asm volatile("cp.async.cg.shared.global [%0], [%1], 16, %2;"
                 :: "r"(dst), "l"(src), "r"(nbytes));
}
__device__ __forceinline__ void mma_f16(float d[4], const uint32_t a[4],
                                        uint32_t b0, uint32_t b1) {
    asm volatile(
        "mma.sync.aligned.m16n8k16.row.col.f32.f16.f16.f32 "
        "{%0,%1,%2,%3}, {%4,%5,%6,%7}, {%8,%9}, {%0,%1,%2,%3};"
        : "+f"(d[0]), "+f"(d[1]), "+f"(d[2]), "+f"(d[3])
        : "r"(a[0]), "r"(a[1]), "r"(a[2]), "r"(a[3]), "r"(b0), "r"(b1));
}

// ---------------------------------------------------------------------------
// Kernel 0: convert W to fp16 (rn). 16384 float4s.
// ---------------------------------------------------------------------------
__global__ __launch_bounds__(256) void wconv_kernel(const float4* __restrict__ W) {
    const int i = blockIdx.x * 256 + threadIdx.x;
    float4 v = W[i];
    __half2* d = (__half2*)(g_Wh + (size_t)i * 4);
    d[0] = __floats2half2_rn(v.x, v.y);
    d[1] = __floats2half2_rn(v.z, v.w);
}

// ---------------------------------------------------------------------------
// Kernel 1: h = x @ W.T + b (row 0 zeroed), fp16 mma m16n8k16 -> fp16 h.
// A path: LDG fp32 x + cvt + STS (register-prefetched 1 chunk ahead).
// B path: cp.async fp16 W, 2-stage. TWO barriers per chunk (race-free: the
// trailing barrier of chunk c-1 orders all reads of buffer s^1 before chunk
// c's cp.async writes into it).
// ---------------------------------------------------------------------------
__global__ __launch_bounds__(256, 2) void gemm_kernel(
    const float* __restrict__ x, const float* __restrict__ bias, int M)
{
    __shared__ uint32_t sA[2][BM][RW];
    __shared__ uint32_t sB[2][BN][RW];

    const int tid  = threadIdx.x;
    const int bn   = blockIdx.x * BN;   // grid.x = 2
    const int bm   = blockIdx.y * BM;
    const int warp = tid >> 5, lane = tid & 31;
    const int wr   = (warp >> 1) * 32;
    const int wc   = (warp & 1) * 64;
    const int g    = lane >> 2,  tg = lane & 3;
    const int sel  = lane >> 3,  r8 = lane & 7;

    const uint32_t sAu = smem_u32(sA), sBu = smem_u32(sB);

    // ---- A fill: thread t -> row t&127, 32B-half t>>7 (16 halfs / 16 floats)
    const int arow = tid & 127;
    const int ahf  = tid >> 7;
    const float* xs = x + (size_t)(bm + arow) * DD + ahf * 16;
    const bool  av  = (bm + arow) < M;
    const uint32_t dA = sAu + (uint32_t)((arow * RW + ahf * 8) * 4);

    // ---- B fill via cp.async: thread t -> rows (t>>2),(t>>2)+64, 16B chunk t&3
    const int crow = tid >> 2;
    const int cch  = tid & 3;
    const __half* ws0 = g_Wh + (size_t)(bn + crow)      * DD + cch * 8;
    const __half* ws1 = g_Wh + (size_t)(bn + crow + 64) * DD + cch * 8;
    const uint32_t dB0 = sBu + (uint32_t)((crow       * RW + cch * 4) * 4);
    const uint32_t dB1 = sBu + (uint32_t)(((crow + 64) * RW + cch * 4) * 4);

    // ldmatrix per-lane base addresses
    uint32_t aBase[2], bBase[4];
    #pragma unroll
    for (int mi = 0; mi < 2; mi++) {
        const int row = wr + mi * 16 + (sel & 1) * 8 + r8;
        aBase[mi] = sAu + (uint32_t)((row * RW + (sel >> 1) * 4) * 4);
    }
    #pragma unroll
    for (int p = 0; p < 4; p++) {
        const int row = wc + p * 16 + (sel & 1) * 8 + r8;
        bBase[p] = sBu + (uint32_t)((row * RW + (sel >> 1) * 4) * 4);
    }

    float acc[2][8][4];
    #pragma unroll
    for (int mi = 0; mi < 2; mi++)
        #pragma unroll
        for (int ni = 0; ni < 8; ni++)
            #pragma unroll
            for (int e = 0; e < 4; e++) acc[mi][ni][e] = 0.f;

    const float4 z4 = make_float4(0.f, 0.f, 0.f, 0.f);
    float4 ra[4];

    auto loadA = [&](int c) {
        #pragma unroll
        for (int i = 0; i < 4; i++)
            ra[i] = av ? *(const float4*)(xs + c * BKH + i * 4) : z4;
    };
    auto storeA = [&](int s) {
        const uint32_t ad = dA + (uint32_t)(s * BM * RW * 4);
        uint4 u0, u1;
        u0.x = h2u(__floats2half2_rn(ra[0].x, ra[0].y));
        u0.y = h2u(__floats2half2_rn(ra[0].z, ra[0].w));
        u0.z = h2u(__floats2half2_rn(ra[1].x, ra[1].y));
        u0.w = h2u(__floats2half2_rn(ra[1].z, ra[1].w));
        u1.x = h2u(__floats2half2_rn(ra[2].x, ra[2].y));
        u1.y = h2u(__floats2half2_rn(ra[2].z, ra[2].w));
        u1.z = h2u(__floats2half2_rn(ra[3].x, ra[3].y));
        u1.w = h2u(__floats2half2_rn(ra[3].z, ra[3].w));
        asm volatile("st.shared.v4.b32 [%0], {%1,%2,%3,%4};"
                     :: "r"(ad), "r"(u0.x), "r"(u0.y), "r"(u0.z), "r"(u0.w));
        asm volatile("st.shared.v4.b32 [%0], {%1,%2,%3,%4};"
                     :: "r"(ad + 16), "r"(u1.x), "r"(u1.y), "r"(u1.z), "r"(u1.w));
    };
    auto issueB = [&](int c, int s) {
        const uint32_t bo = (uint32_t)(s * BN * RW * 4);
        const int ko = c * BKH;
        cp16(dB0 + bo, ws0 + ko, 16u);
        cp16(dB1 + bo, ws1 + ko, 16u);
    };

    // ---- prologue: chunk 0 A+B into buf 0; prefetch A chunk 1 into regs
    loadA(0);
    issueB(0, 0); asm volatile("cp.async.commit_group;" ::: "memory");
    storeA(0);
    loadA(1);

    #pragma unroll 1
    for (int c = 0; c < NCHH; c++) {
        const int s = c & 1;
        if (c + 1 < NCHH) {
            // safe: trailing barrier of chunk c-1 ordered all reads of buf s^1
            issueB(c + 1, s ^ 1);
            asm volatile("cp.async.commit_group;" ::: "memory");
            asm volatile("cp.async.wait_group 1;" ::: "memory");
        } else {
            asm volatile("cp.async.wait_group 0;" ::: "memory");
        }
        __syncthreads();   // (1) A(c)+B(c) visible in buf s

        const uint32_t ao = (uint32_t)(s * BM * RW * 4);
        const uint32_t bo = (uint32_t)(s * BN * RW * 4);
        #pragma unroll
        for (int ks = 0; ks < 2; ks++) {
            const uint32_t kb = (uint32_t)(ks * 32);
            uint32_t af[2][4], bf[4][4];
            ldsm4(af[0], aBase[0] + ao + kb);
            ldsm4(af[1], aBase[1] + ao + kb);
            #pragma unroll
            for (int p = 0; p < 4; p++) ldsm4(bf[p], bBase[p] + bo + kb);
            #pragma unroll
            for (int mi = 0; mi < 2; mi++) {
                #pragma unroll
                for (int p = 0; p < 4; p++) {
                    mma_f16(acc[mi][p * 2 + 0], af[mi], bf[p][0], bf[p][2]);
                    mma_f16(acc[mi][p * 2 + 1], af[mi], bf[p][1], bf[p][3]);
                }
            }
        }

        if (c + 1 < NCHH) {
            storeA(s ^ 1);             // A for chunk c+1 (other buffer: no race)
            if (c + 2 < NCHH) loadA(c + 2);
        }
        __syncthreads();   // (2) all reads of buf s done before next iter writes it
    }

    // epilogue: + bias, zero row 0, store fp16
    #pragma unroll
    for (int mi = 0; mi < 2; mi++) {
        #pragma unroll
        for (int ni = 0; ni < 8; ni++) {
            const int col = bn + wc + ni * 8 + tg * 2;
            const float b0 = bias[col];
            const float b1 = bias[col + 1];
            const int r0 = bm + wr + mi * 16 + g;
            const int r1 = r0 + 8;
            if (r0 < M) {
                const float v0 = (r0 == 0) ? 0.f : acc[mi][ni][0] + b0;
                const float v1 = (r0 == 0) ? 0.f : acc[mi][ni][1] + b1;
                *(__half2*)(g_hh + (size_t)r0 * DD + col) = __floats2half2_rn(v0, v1);
            }
            if (r1 < M) {
                *(__half2*)(g_hh + (size_t)r1 * DD + col) =
                    __floats2half2_rn(acc[mi][ni][2] + b0, acc[mi][ni][3] + b1);
            }
        }
    }
}

// ---------------------------------------------------------------------------
// Kernel 2: out[i] = relu(h[i] + sum_k h[b_from_a[a_from_b[i][k]]])
// One warp per atom; lane covers 8 halfs (16B). fp32 accumulation.
// ---------------------------------------------------------------------------
__global__ __launch_bounds__(256) void agg_kernel(
    const int* __restrict__ b_from_a, const int* __restrict__ a_from_b,
    float* __restrict__ out, int M)
{
    const int atom = blockIdx.x * 8 + (threadIdx.x >> 5);
    if (atom >= M) return;
    const int lane = threadIdx.x & 31;

    int aidx = 0;
    if (lane < NB) {
        const int bond = __ldg(a_from_b + (size_t)atom * NB + lane);
        aidx = __ldg(b_from_a + bond);
    }

    const uint4* h16 = (const uint4*)g_hh;    // 16B = 8 halfs; row = 32 uint4
    uint4 self = __ldg(h16 + (size_t)atom * 32 + lane);

    float acc[8];
    {
        const __half2* p = (const __half2*)&self;
        #pragma unroll
        for (int j = 0; j < 4; j++) {
            float2 f = __half22float2(p[j]);
            acc[j * 2] = f.x; acc[j * 2 + 1] = f.y;
        }
    }

    #pragma unroll
    for (int k = 0; k < NB; k++) {
        const int idx = __shfl_sync(0xFFFFFFFFu, aidx, k);
        uint4 v = __ldg(h16 + (size_t)idx * 32 + lane);
        const __half2* p = (const __half2*)&v;
        #pragma unroll
        for (int j = 0; j < 4; j++) {
            float2 f = __half22float2(p[j]);
            acc[j * 2] += f.x; acc[j * 2 + 1] += f.y;
        }
    }

    float4 o0, o1;
    o0.x = fmaxf(acc[0], 0.f); o0.y = fmaxf(acc[1], 0.f);
    o0.z = fmaxf(acc[2], 0.f); o0.w = fmaxf(acc[3], 0.f);
    o1.x = fmaxf(acc[4], 0.f); o1.y = fmaxf(acc[5], 0.f);
    o1.z = fmaxf(acc[6], 0.f); o1.w = fmaxf(acc[7], 0.f);
    float4* op = (float4*)(out + (size_t)atom * DD + lane * 8);
    op[0] = o0;
    op[1] = o1;
}

// ---------------------------------------------------------------------------
// Launch: inputs per metadata order: x, W, b, b_from_a, a_from_b
// ---------------------------------------------------------------------------
extern "C" void kernel_launch(void* const* d_in, const int* in_sizes, int n_in,
                              void* d_out, int out_size) {
    const float* x        = (const float*)d_in[0];
    const float* W        = (const float*)d_in[1];
    const float* bias     = (const float*)d_in[2];
    const int*   b_from_a = (const int*)d_in[3];
    const int*   a_from_b = (const int*)d_in[4];
    float*       out      = (float*)d_out;

    const int M = in_sizes[0] / DD;   // 50000

    wconv_kernel<<<DD * DD / 1024, 256>>>((const float4*)W);

    dim3 ggrid(DD / BN, (M + BM - 1) / BM);   // (2, 391)
    gemm_kernel<<<ggrid, 256>>>(x, bias, M);

    agg_kernel<<<(M + 7) / 8, 256>>>(b_from_a, a_from_b, out, M);
}

// round 15
// speedup vs baseline: 1.0507x; 1.0507x over previous
#include <cuda_runtime.h>
#include <cuda_fp16.h>
#include <cstdint>

#define MAX_ATOMS 50000
#define DD 256
#define NB 16

#define BM 128
#define BN 128
#define BKH 32            // K chunk in halfs (64 B/row)
#define NCHH (DD / BKH)   // 8 chunks
#define RW 20             // 4B words per smem row (16 data + 4 pad; conflict-free)

// Scratch: fp16 h (row 0 zeroed), fp16 copies of x and W.
__device__ __half g_hh[(size_t)MAX_ATOMS * DD];
__device__ __half g_xh[(size_t)MAX_ATOMS * DD];
__device__ __half g_Wh[DD * DD];

// ---------------------------------------------------------------------------
// helpers (sm_80-baseline features only — harness builds plain sm_103 PTX)
// ---------------------------------------------------------------------------
__device__ __forceinline__ uint32_t smem_u32(const void* p) {
    uint32_t a;
    asm("{ .reg .u64 t; cvta.to.shared.u64 t, %1; cvt.u32.u64 %0, t; }" : "=r"(a) : "l"(p));
    return a;
}
__device__ __forceinline__ void ldsm4(uint32_t r[4], uint32_t a) {
    asm volatile("ldmatrix.sync.aligned.m8n8.x4.shared.b16 {%0,%1,%2,%3}, [%4];"
                 : "=r"(r[0]), "=r"(r[1]), "=r"(r[2]), "=r"(r[3]) : "r"(a));
}
__device__ __forceinline__ void cp16(uint32_t dst, const void* src, uint32_t nbytes) {
    asm volatile("cp.async.cg.shared.global [%0], [%1], 16, %2;"
                 :: "r"(dst), "l"(src), "r"(nbytes));
}
__device__ __forceinline__ void mma_f16(float d[4], const uint32_t a[4],
                                        uint32_t b0, uint32_t b1) {
    asm volatile(
        "mma.sync.aligned.m16n8k16.row.col.f32.f16.f16.f32 "
        "{%0,%1,%2,%3}, {%4,%5,%6,%7}, {%8,%9}, {%0,%1,%2,%3};"
        : "+f"(d[0]), "+f"(d[1]), "+f"(d[2]), "+f"(d[3])
        : "r"(a[0]), "r"(a[1]), "r"(a[2]), "r"(a[3]), "r"(b0), "r"(b1));
}

// ---------------------------------------------------------------------------
// Kernel 0: convert x and W to fp16 (rn). 4 float4 per thread, MLP=4.
// Blocks [0, nbx) cover x (nbx = nx4/1024); blocks [nbx, nbx+16) cover W.
// ---------------------------------------------------------------------------
__global__ __launch_bounds__(256) void conv_kernel(
    const float4* __restrict__ x, const float4* __restrict__ W, int nbx)
{
    const int b = blockIdx.x;
    const int tid = threadIdx.x;
    if (b < nbx) {
        const int base = b * 1024 + tid;
        float4 v0 = x[base];
        float4 v1 = x[base + 256];
        float4 v2 = x[base + 512];
        float4 v3 = x[base + 768];
        __half2* d = (__half2*)g_xh;
        d[(size_t)(base)       * 2 + 0] = __floats2half2_rn(v0.x, v0.y);
        d[(size_t)(base)       * 2 + 1] = __floats2half2_rn(v0.z, v0.w);
        d[(size_t)(base + 256) * 2 + 0] = __floats2half2_rn(v1.x, v1.y);
        d[(size_t)(base + 256) * 2 + 1] = __floats2half2_rn(v1.z, v1.w);
        d[(size_t)(base + 512) * 2 + 0] = __floats2half2_rn(v2.x, v2.y);
        d[(size_t)(base + 512) * 2 + 1] = __floats2half2_rn(v2.z, v2.w);
        d[(size_t)(base + 768) * 2 + 0] = __floats2half2_rn(v3.x, v3.y);
        d[(size_t)(base + 768) * 2 + 1] = __floats2half2_rn(v3.z, v3.w);
    } else {
        const int base = (b - nbx) * 1024 + tid;
        __half2* d = (__half2*)g_Wh;
        #pragma unroll
        for (int i = 0; i < 4; i++) {
            const int j = base + i * 256;
            float4 v = W[j];
            d[(size_t)j * 2 + 0] = __floats2half2_rn(v.x, v.y);
            d[(size_t)j * 2 + 1] = __floats2half2_rn(v.z, v.w);
        }
    }
}

// ---------------------------------------------------------------------------
// Kernel 1: h = x @ W.T + b (row 0 zeroed), fp16 mma m16n8k16 -> fp16 h.
// 256 threads = 8 warps (4x2), block tile 128x128, warp tile 32x64.
// 2-stage cp.async pipeline, BK=32 halfs, 8 chunks. (Proven R9 structure.)
// ---------------------------------------------------------------------------
__global__ __launch_bounds__(256, 2) void gemm_kernel(
    const float* __restrict__ bias, int M)
{
    __shared__ uint32_t sA[2][BM][RW];
    __shared__ uint32_t sB[2][BN][RW];

    const int tid  = threadIdx.x;
    const int bn   = blockIdx.x * BN;   // grid.x = 2
    const int bm   = blockIdx.y * BM;
    const int warp = tid >> 5, lane = tid & 31;
    const int wr   = (warp >> 1) * 32;
    const int wc   = (warp & 1) * 64;
    const int g    = lane >> 2,  tg = lane & 3;
    const int sel  = lane >> 3,  r8 = lane & 7;

    const uint32_t sAu = smem_u32(sA), sBu = smem_u32(sB);

    // cp.async mapping: thread t -> rows (t>>2) and (t>>2)+64, 16B chunk t&3.
    const int crow = tid >> 2;          // 0..63
    const int cch  = tid & 3;           // 16B chunk within 64B row
    const __half* xs0 = g_xh + (size_t)(bm + crow)      * DD + cch * 8;
    const __half* xs1 = g_xh + (size_t)(bm + crow + 64) * DD + cch * 8;
    const __half* ws0 = g_Wh + (size_t)(bn + crow)      * DD + cch * 8;
    const __half* ws1 = g_Wh + (size_t)(bn + crow + 64) * DD + cch * 8;
    const uint32_t nb0 = (bm + crow      < M) ? 16u : 0u;
    const uint32_t nb1 = (bm + crow + 64 < M) ? 16u : 0u;
    const uint32_t dA0 = sAu + (uint32_t)((crow       * RW + cch * 4) * 4);
    const uint32_t dA1 = sAu + (uint32_t)(((crow + 64) * RW + cch * 4) * 4);
    const uint32_t dB0 = sBu + (uint32_t)((crow       * RW + cch * 4) * 4);
    const uint32_t dB1 = sBu + (uint32_t)(((crow + 64) * RW + cch * 4) * 4);

    // ldmatrix per-lane base addresses (16B chunk = 4 words)
    uint32_t aBase[2], bBase[4];
    #pragma unroll
    for (int mi = 0; mi < 2; mi++) {
        const int row = wr + mi * 16 + (sel & 1) * 8 + r8;
        aBase[mi] = sAu + (uint32_t)((row * RW + (sel >> 1) * 4) * 4);
    }
    #pragma unroll
    for (int p = 0; p < 4; p++) {
        const int row = wc + p * 16 + (sel & 1) * 8 + r8;
        bBase[p] = sBu + (uint32_t)((row * RW + (sel >> 1) * 4) * 4);
    }

    float acc[2][8][4];
    #pragma unroll
    for (int mi = 0; mi < 2; mi++)
        #pragma unroll
        for (int ni = 0; ni < 8; ni++)
            #pragma unroll
            for (int e = 0; e < 4; e++) acc[mi][ni][e] = 0.f;

    auto issue = [&](int c, int s) {
        const uint32_t ao = (uint32_t)(s * BM * RW * 4);
        const uint32_t bo = (uint32_t)(s * BN * RW * 4);
        const int ko = c * BKH;
        cp16(dA0 + ao, xs0 + ko, nb0);
        cp16(dA1 + ao, xs1 + ko, nb1);
        cp16(dB0 + bo, ws0 + ko, 16u);
        cp16(dB1 + bo, ws1 + ko, 16u);
    };

    issue(0, 0); asm volatile("cp.async.commit_group;" ::: "memory");

    #pragma unroll 1
    for (int c = 0; c < NCHH; c++) {
        const int s = c & 1;
        if (c + 1 < NCHH) {
            issue(c + 1, (c + 1) & 1);
            asm volatile("cp.async.commit_group;" ::: "memory");
            asm volatile("cp.async.wait_group 1;" ::: "memory");
        } else {
            asm volatile("cp.async.wait_group 0;" ::: "memory");
        }
        __syncthreads();

        const uint32_t ao = (uint32_t)(s * BM * RW * 4);
        const uint32_t bo = (uint32_t)(s * BN * RW * 4);
        #pragma unroll
        for (int ks = 0; ks < 2; ks++) {
            const uint32_t kb = (uint32_t)(ks * 32);
            uint32_t af[2][4], bf[4][4];
            ldsm4(af[0], aBase[0] + ao + kb);
            ldsm4(af[1], aBase[1] + ao + kb);
            #pragma unroll
            for (int p = 0; p < 4; p++) ldsm4(bf[p], bBase[p] + bo + kb);
            #pragma unroll
            for (int mi = 0; mi < 2; mi++) {
                #pragma unroll
                for (int p = 0; p < 4; p++) {
                    mma_f16(acc[mi][p * 2 + 0], af[mi], bf[p][0], bf[p][2]);
                    mma_f16(acc[mi][p * 2 + 1], af[mi], bf[p][1], bf[p][3]);
                }
            }
        }
        __syncthreads();
    }

    // epilogue: + bias, zero row 0, store fp16
    #pragma unroll
    for (int mi = 0; mi < 2; mi++) {
        #pragma unroll
        for (int ni = 0; ni < 8; ni++) {
            const int col = bn + wc + ni * 8 + tg * 2;
            const float b0 = bias[col];
            const float b1 = bias[col + 1];
            const int r0 = bm + wr + mi * 16 + g;
            const int r1 = r0 + 8;
            if (r0 < M) {
                const float v0 = (r0 == 0) ? 0.f : acc[mi][ni][0] + b0;
                const float v1 = (r0 == 0) ? 0.f : acc[mi][ni][1] + b1;
                *(__half2*)(g_hh + (size_t)r0 * DD + col) = __floats2half2_rn(v0, v1);
            }
            if (r1 < M) {
                *(__half2*)(g_hh + (size_t)r1 * DD + col) =
                    __floats2half2_rn(acc[mi][ni][2] + b0, acc[mi][ni][3] + b1);
            }
        }
    }
}

// ---------------------------------------------------------------------------
// Kernel 2: out[i] = relu(h[i] + sum_k h[b_from_a[a_from_b[i][k]]])
// One warp per atom; lane covers 8 halfs (16B). fp32 accumulation.
// Output stores use .cs (streaming) to keep g_hh resident in L2.
// ---------------------------------------------------------------------------
__global__ __launch_bounds__(256) void agg_kernel(
    const int* __restrict__ b_from_a, const int* __restrict__ a_from_b,
    float* __restrict__ out, int M)
{
    const int atom = blockIdx.x * 8 + (threadIdx.x >> 5);
    if (atom >= M) return;
    const int lane = threadIdx.x & 31;

    int aidx = 0;
    if (lane < NB) {
        const int bond = __ldg(a_from_b + (size_t)atom * NB + lane);
        aidx = __ldg(b_from_a + bond);
    }

    const uint4* h16 = (const uint4*)g_hh;    // 16B = 8 halfs; row = 32 uint4
    uint4 self = __ldg(h16 + (size_t)atom * 32 + lane);

    float acc[8];
    {
        const __half2* p = (const __half2*)&self;
        #pragma unroll
        for (int j = 0; j < 4; j++) {
            float2 f = __half22float2(p[j]);
            acc[j * 2] = f.x; acc[j * 2 + 1] = f.y;
        }
    }

    #pragma unroll
    for (int k = 0; k < NB; k++) {
        const int idx = __shfl_sync(0xFFFFFFFFu, aidx, k);
        uint4 v = __ldg(h16 + (size_t)idx * 32 + lane);
        const __half2* p = (const __half2*)&v;
        #pragma unroll
        for (int j = 0; j < 4; j++) {
            float2 f = __half22float2(p[j]);
            acc[j * 2] += f.x; acc[j * 2 + 1] += f.y;
        }
    }

    float4 o0, o1;
    o0.x = fmaxf(acc[0], 0.f); o0.y = fmaxf(acc[1], 0.f);
    o0.z = fmaxf(acc[2], 0.f); o0.w = fmaxf(acc[3], 0.f);
    o1.x = fmaxf(acc[4], 0.f); o1.y = fmaxf(acc[5], 0.f);
    o1.z = fmaxf(acc[6], 0.f); o1.w = fmaxf(acc[7], 0.f);
    float4* op = (float4*)(out + (size_t)atom * DD + lane * 8);
    __stcs(op,     o0);
    __stcs(op + 1, o1);
}

// ---------------------------------------------------------------------------
// Launch: inputs per metadata order: x, W, b, b_from_a, a_from_b
// ---------------------------------------------------------------------------
extern "C" void kernel_launch(void* const* d_in, const int* in_sizes, int n_in,
                              void* d_out, int out_size) {
    const float* x        = (const float*)d_in[0];
    const float* W        = (const float*)d_in[1];
    const float* bias     = (const float*)d_in[2];
    const int*   b_from_a = (const int*)d_in[3];
    const int*   a_from_b = (const int*)d_in[4];
    float*       out      = (float*)d_out;

    const int M = in_sizes[0] / DD;       // 50000
    const int nx4 = in_sizes[0] / 4;      // 3,200,000 float4
    const int nbx = nx4 / 1024;           // 3125 x-blocks (exact)
    const int nbw = (DD * DD / 4) / 1024; // 16 W-blocks

    conv_kernel<<<nbx + nbw, 256>>>((const float4*)x, (const float4*)W, nbx);

    dim3 ggrid(DD / BN, (M + BM - 1) / BM);   // (2, 391)
    gemm_kernel<<<ggrid, 256>>>(bias, M);

    agg_kernel<<<(M + 7) / 8, 256>>>(b_from_a, a_from_b, out, M);
}